// round 14
// baseline (speedup 1.0000x reference)
#include <cuda_runtime.h>
#include <cuda.h>
#include <cuda_fp16.h>
#include <cstdint>

#define TOK  2048
#define HID  2048
#define FFN  5632
#define NEXP 8
#define NSTG 3
#define STAGE_BYTES 65536          // A fp16 32KB + B fp16 32KB
#define SMEM_REQ (1024 + NSTG * STAGE_BYTES + 256)

// ---- arch feature gate ----
#if !defined(__CUDA_ARCH__)
#  define TC_OK 1
#elif defined(__CUDA_ARCH_FEAT_SM103_ALL) || defined(__CUDA_ARCH_FEAT_SM100_ALL) || \
      defined(__CUDA_ARCH_FEAT_SM101_ALL) || \
      (defined(__CUDA_ARCH_SPECIFIC__) && (__CUDA_ARCH_SPECIFIC__ >= 1000)) || \
      (defined(__CUDA_ARCH_FAMILY_SPECIFIC__) && (__CUDA_ARCH_FAMILY_SPECIFIC__ >= 1000))
#  define TC_OK 1
#else
#  define TC_OK 0
#endif

// ---------------- static scratch ----------------
__device__ int   g_counts[NEXP];
__device__ int   g_slot[TOK * 2];
__device__ float g_wt[TOK * 2];
__device__ __align__(1024) __half g_xg[(size_t)NEXP * TOK * HID];
__device__ __align__(1024) __half g_w13h[(size_t)NEXP * FFN * 2 * HID];
__device__ __align__(1024) __half g_w2h[(size_t)NEXP * HID * FFN];
__device__ __align__(1024) __half g_h[(size_t)NEXP * TOK * FFN];
__device__ __align__(1024) float  g_y[(size_t)NEXP * TOK * HID];

// ---------------- PTX helpers ----------------
__device__ __forceinline__ uint32_t smem_u32(const void* p) {
    uint32_t a;
    asm("{ .reg .u64 t; cvta.to.shared.u64 t, %1; cvt.u32.u64 %0, t; }" : "=r"(a) : "l"(p));
    return a;
}
__device__ __forceinline__ void mbar_init(uint32_t a, uint32_t cnt) {
    asm volatile("mbarrier.init.shared.b64 [%0], %1;" :: "r"(a), "r"(cnt) : "memory");
}
__device__ __forceinline__ void mbar_expect_tx(uint32_t a, uint32_t bytes) {
    asm volatile("mbarrier.arrive.expect_tx.shared.b64 _, [%0], %1;" :: "r"(a), "r"(bytes) : "memory");
}
__device__ __forceinline__ void mbar_wait(uint32_t a, uint32_t phase) {
    uint32_t done;
    asm volatile(
        "{\n\t.reg .pred p;\n\t"
        "mbarrier.try_wait.parity.acquire.cta.shared::cta.b64 p, [%1], %2;\n\t"
        "selp.b32 %0, 1, 0, p;\n\t}"
        : "=r"(done) : "r"(a), "r"(phase) : "memory");
    if (!done) {
        asm volatile(
            "{\n\t.reg .pred P1;\n\t"
            "W_%=:\n\t"
            "mbarrier.try_wait.parity.acquire.cta.shared::cta.b64 P1, [%0], %1, 0x989680;\n\t"
            "@P1 bra.uni D_%=;\n\t"
            "bra.uni W_%=;\n\t"
            "D_%=:\n\t}"
            :: "r"(a), "r"(phase) : "memory");
    }
}
__device__ __forceinline__ void tma3(uint32_t smem_dst, const CUtensorMap* tm,
                                     int cx, int cy, int cz, uint32_t mbar) {
    asm volatile(
        "cp.async.bulk.tensor.3d.shared::cta.global.tile.mbarrier::complete_tx::bytes "
        "[%0], [%1, {%2, %3, %4}], [%5];"
        :: "r"(smem_dst), "l"(tm), "r"(cx), "r"(cy), "r"(cz), "r"(mbar) : "memory");
}
__device__ __forceinline__ void tc_alloc(uint32_t smem_result, uint32_t ncols) {
    asm volatile("tcgen05.alloc.cta_group::1.sync.aligned.shared::cta.b32 [%0], %1;"
                 :: "r"(smem_result), "r"(ncols) : "memory");
}
__device__ __forceinline__ void tc_dealloc(uint32_t tmem, uint32_t ncols) {
    asm volatile("tcgen05.dealloc.cta_group::1.sync.aligned.b32 %0, %1;" :: "r"(tmem), "r"(ncols));
}
__device__ __forceinline__ void tc_commit(uint32_t mbar) {
    asm volatile("tcgen05.commit.cta_group::1.mbarrier::arrive::one.shared::cluster.b64 [%0];"
                 :: "r"(mbar) : "memory");
}
__device__ __forceinline__ void tc_fence_after() {
    asm volatile("tcgen05.fence::after_thread_sync;" ::: "memory");
}
__device__ __forceinline__ void tc_fence_before() {
    asm volatile("tcgen05.fence::before_thread_sync;" ::: "memory");
}
__device__ __forceinline__ void tc_wait_ld() {
    asm volatile("tcgen05.wait::ld.sync.aligned;" ::: "memory");
}
__device__ __forceinline__ void mma_f16_ss(uint32_t d, uint64_t ad, uint64_t bd,
                                           uint32_t idesc, uint32_t en) {
    asm volatile(
        "{\n\t.reg .pred p;\n\t"
        "setp.ne.u32 p, %4, 0;\n\t"
        "tcgen05.mma.cta_group::1.kind::f16 [%0], %1, %2, %3, {%5, %5, %5, %5}, p;\n\t}"
        :: "r"(d), "l"(ad), "l"(bd), "r"(idesc), "r"(en), "r"(0u) : "memory");
}
#define LDTM32(r, addr) \
    asm volatile("tcgen05.ld.sync.aligned.32x32b.x32.b32 " \
        "{%0,%1,%2,%3,%4,%5,%6,%7,%8,%9,%10,%11,%12,%13,%14,%15," \
        "%16,%17,%18,%19,%20,%21,%22,%23,%24,%25,%26,%27,%28,%29,%30,%31}, [%32];" \
        : "=r"((r)[0]),"=r"((r)[1]),"=r"((r)[2]),"=r"((r)[3]),"=r"((r)[4]),"=r"((r)[5]), \
          "=r"((r)[6]),"=r"((r)[7]),"=r"((r)[8]),"=r"((r)[9]),"=r"((r)[10]),"=r"((r)[11]), \
          "=r"((r)[12]),"=r"((r)[13]),"=r"((r)[14]),"=r"((r)[15]),"=r"((r)[16]),"=r"((r)[17]), \
          "=r"((r)[18]),"=r"((r)[19]),"=r"((r)[20]),"=r"((r)[21]),"=r"((r)[22]),"=r"((r)[23]), \
          "=r"((r)[24]),"=r"((r)[25]),"=r"((r)[26]),"=r"((r)[27]),"=r"((r)[28]),"=r"((r)[29]), \
          "=r"((r)[30]),"=r"((r)[31]) : "r"(addr))

static constexpr uint64_t DESC_BASE_SW128 =
    (uint64_t(2) << 61) | (uint64_t(1) << 46) | (uint64_t(64) << 32) | (uint64_t(1) << 16);
__device__ __forceinline__ uint64_t smem_desc(uint32_t addr) {
    return DESC_BASE_SW128 | ((uint64_t)(addr >> 4) & 0x3FFF);
}
#define IDESC ((1u << 4) | (32u << 17) | (8u << 24))

// ---------------- small kernels ----------------
__global__ void zero_counts_kernel() { if (threadIdx.x < NEXP) g_counts[threadIdx.x] = 0; }

__global__ void conv_w13_kernel(const float* __restrict__ w1, const float* __restrict__ w3, int ebase) {
    int e = ebase + blockIdx.z;
    int v = blockIdx.x * blockDim.x + threadIdx.x;
    int rr = v >> 8;
    int c8 = (v & 255) * 8;
    int f = rr >> 1;
    const float* src = ((rr & 1) ? w3 : w1) + ((size_t)e * FFN + f) * HID + c8;
    float4 f0 = reinterpret_cast<const float4*>(src)[0];
    float4 f1 = reinterpret_cast<const float4*>(src)[1];
    __half2 h0 = __floats2half2_rn(f0.x, f0.y), h1 = __floats2half2_rn(f0.z, f0.w);
    __half2 h2 = __floats2half2_rn(f1.x, f1.y), h3 = __floats2half2_rn(f1.z, f1.w);
    uint4 u = { *(unsigned*)&h0, *(unsigned*)&h1, *(unsigned*)&h2, *(unsigned*)&h3 };
    *reinterpret_cast<uint4*>(g_w13h + ((size_t)e * FFN * 2 + rr) * HID + c8) = u;
}

__global__ void conv_w2_kernel(const float* __restrict__ w2) {
    int e = blockIdx.z;
    int v = blockIdx.x * blockDim.x + threadIdx.x;
    int row = v / (FFN / 8);
    int c8 = (v % (FFN / 8)) * 8;
    const float* src = w2 + ((size_t)e * HID + row) * FFN + c8;
    float4 f0 = reinterpret_cast<const float4*>(src)[0];
    float4 f1 = reinterpret_cast<const float4*>(src)[1];
    __half2 h0 = __floats2half2_rn(f0.x, f0.y), h1 = __floats2half2_rn(f0.z, f0.w);
    __half2 h2 = __floats2half2_rn(f1.x, f1.y), h3 = __floats2half2_rn(f1.z, f1.w);
    uint4 u = { *(unsigned*)&h0, *(unsigned*)&h1, *(unsigned*)&h2, *(unsigned*)&h3 };
    *reinterpret_cast<uint4*>(g_w2h + ((size_t)e * HID + row) * FFN + c8) = u;
}

// router + fused scatter
__global__ void router_kernel(const float* __restrict__ x, const float* __restrict__ wg) {
    int gw   = (blockIdx.x * blockDim.x + threadIdx.x) >> 5;
    int lane = threadIdx.x & 31;
    if (gw >= TOK) return;
    const float4* xr = reinterpret_cast<const float4*>(x + (size_t)gw * HID);
    float acc[NEXP];
#pragma unroll
    for (int e = 0; e < NEXP; e++) acc[e] = 0.f;
#pragma unroll 4
    for (int it = 0; it < 16; it++) {
        float4 xv = xr[lane + 32 * it];
#pragma unroll
        for (int e = 0; e < NEXP; e++) {
            float4 w = reinterpret_cast<const float4*>(wg + e * HID)[lane + 32 * it];
            acc[e] += xv.x * w.x + xv.y * w.y + xv.z * w.z + xv.w * w.w;
        }
    }
#pragma unroll
    for (int e = 0; e < NEXP; e++) {
#pragma unroll
        for (int o = 16; o > 0; o >>= 1) acc[e] += __shfl_xor_sync(0xffffffffu, acc[e], o);
    }
    int e0 = 0, e1 = 0, q0 = 0, q1 = 0;
    if (lane == 0) {
        float m = acc[0];
#pragma unroll
        for (int e = 1; e < NEXP; e++) m = fmaxf(m, acc[e]);
        float p[NEXP];
#pragma unroll
        for (int e = 0; e < NEXP; e++) p[e] = __expf(acc[e] - m);
        e0 = 0;
#pragma unroll
        for (int e = 1; e < NEXP; e++) if (p[e] > p[e0]) e0 = e;
        e1 = (e0 == 0) ? 1 : 0;
#pragma unroll
        for (int e = 0; e < NEXP; e++) if (e != e0 && p[e] > p[e1]) e1 = e;
        float s  = p[e0] + p[e1];
        q0 = atomicAdd(&g_counts[e0], 1);
        q1 = atomicAdd(&g_counts[e1], 1);
        g_slot[2 * gw]     = e0 * TOK + q0;  g_wt[2 * gw]     = p[e0] / s;
        g_slot[2 * gw + 1] = e1 * TOK + q1;  g_wt[2 * gw + 1] = p[e1] / s;
    }
    e0 = __shfl_sync(0xffffffffu, e0, 0);
    e1 = __shfl_sync(0xffffffffu, e1, 0);
    q0 = __shfl_sync(0xffffffffu, q0, 0);
    q1 = __shfl_sync(0xffffffffu, q1, 0);
    uint2* d0 = reinterpret_cast<uint2*>(g_xg + ((size_t)e0 * TOK + q0) * HID);
    uint2* d1 = reinterpret_cast<uint2*>(g_xg + ((size_t)e1 * TOK + q1) * HID);
#pragma unroll 4
    for (int it = 0; it < 16; it++) {
        float4 xv = xr[lane + 32 * it];
        __half2 h0 = __floats2half2_rn(xv.x, xv.y);
        __half2 h1 = __floats2half2_rn(xv.z, xv.w);
        uint2 u = { *(unsigned*)&h0, *(unsigned*)&h1 };
        d0[lane + 32 * it] = u;
        d1[lane + 32 * it] = u;
    }
}

// zero the pad rows [cnt, ceil256(cnt))
__global__ void pad_kernel() {
    int e = blockIdx.y;
    int cnt = g_counts[e];
    int cc = (cnt + 255) & ~255;
    int row = cnt + blockIdx.x;
    if (row >= cc) return;
    uint4 z = {0u, 0u, 0u, 0u};
    reinterpret_cast<uint4*>(g_xg + ((size_t)e * TOK + row) * HID)[threadIdx.x] = z;
}

// ======================= tcgen05 GEMMs: M=256, N=256, K-stage=64, all-TMA =======================
// CTA raster: blockIdx.x = TOKEN tile (fast) so concurrent CTAs share B tiles via L2,
// and A (small, per-expert) stays L2-resident across n-tiles. B streams from DRAM once.

__global__ __launch_bounds__(256, 1) void gemm13_kernel(
    int ebase, const __grid_constant__ CUtensorMap tmA, const __grid_constant__ CUtensorMap tmB) {
    const int e = ebase + blockIdx.z;
    const int cnt = g_counts[e];
    const int posBase = blockIdx.x * 256;       // token tile (fast dim)
    if (posBase >= cnt) return;
    const int nBase = blockIdx.y * 256;         // interleaved w13 row base
    const int fBaseF = blockIdx.y * 128;        // ffn col base
    const int tid = threadIdx.x, wid = tid >> 5, lid = tid & 31;

#if TC_OK
    extern __shared__ char smem_raw[];
    uint32_t sb = smem_u32(smem_raw);
    sb = (sb + 1023) & ~1023u;
    const uint32_t BAR = sb + NSTG * STAGE_BYTES;

    if (tid == 0) {
#pragma unroll
        for (int s = 0; s < NSTG; s++) {
            mbar_init(BAR + 16 + 8 * s, 1);
            mbar_init(BAR + 48 + 8 * s, 1);
        }
        mbar_init(BAR + 80, 1);
    }
    if (wid == 0) tc_alloc(BAR, 512);
    __syncthreads();
    uint32_t tmem;
    asm volatile("ld.shared.b32 %0, [%1];" : "=r"(tmem) : "r"(BAR));

    const int NT = HID / 64;
    if (tid == 0) {
        int s = 0, ph = 1;
        for (int it = 0; it < NT; it++) {
            mbar_wait(BAR + 48 + 8 * s, ph);
            mbar_expect_tx(BAR + 16 + 8 * s, STAGE_BYTES);
            tma3(sb + s * STAGE_BYTES,         &tmA, it * 64, posBase, e, BAR + 16 + 8 * s);
            tma3(sb + s * STAGE_BYTES + 32768, &tmB, it * 64, nBase,   e, BAR + 16 + 8 * s);
            if (++s == NSTG) { s = 0; ph ^= 1; }
        }
    } else if (tid == 32) {
        tc_fence_after();
        int s = 0, ph = 0;
        for (int it = 0; it < NT; it++) {
            mbar_wait(BAR + 16 + 8 * s, ph);
            uint64_t ad = smem_desc(sb + s * STAGE_BYTES);
            uint64_t bd = smem_desc(sb + s * STAGE_BYTES + 32768);
#pragma unroll
            for (int k = 0; k < 4; k++) {
                uint32_t en = (it | k) != 0;
                mma_f16_ss(tmem,       ad + k * 2,        bd + k * 2, IDESC, en);
                mma_f16_ss(tmem + 256, ad + 1024 + k * 2, bd + k * 2, IDESC, en);
            }
            tc_commit(BAR + 48 + 8 * s);
            if (++s == NSTG) { s = 0; ph ^= 1; }
        }
        tc_commit(BAR + 80);
    }
    mbar_wait(BAR + 80, 0);
    tc_fence_after();

    const int half = wid >> 2;
    const int p = posBase + half * 128 + (wid & 3) * 32 + lid;
    __half* dst = g_h + ((size_t)e * TOK + p) * FFN + fBaseF;
    const uint32_t tmb = tmem + half * 256;
#pragma unroll
    for (int c = 0; c < 8; c++) {
        uint32_t r[32];
        LDTM32(r, tmb + c * 32);
        tc_wait_ld();
        uint4 u0, u1;
        if (p < cnt) {
            unsigned o[8];
#pragma unroll
            for (int j = 0; j < 8; j++) {
                float a0 = __uint_as_float(r[4 * j + 0]);
                float b0 = __uint_as_float(r[4 * j + 1]);
                float a1 = __uint_as_float(r[4 * j + 2]);
                float b1 = __uint_as_float(r[4 * j + 3]);
                float v0 = (a0 / (1.f + __expf(-a0))) * b0;
                float v1 = (a1 / (1.f + __expf(-a1))) * b1;
                __half2 hh = __floats2half2_rn(v0, v1);
                o[j] = *(unsigned*)&hh;
            }
            u0 = make_uint4(o[0], o[1], o[2], o[3]);
            u1 = make_uint4(o[4], o[5], o[6], o[7]);
        } else {
            u0 = make_uint4(0, 0, 0, 0);
            u1 = make_uint4(0, 0, 0, 0);
        }
        *reinterpret_cast<uint4*>(dst + c * 16)     = u0;
        *reinterpret_cast<uint4*>(dst + c * 16 + 8) = u1;
    }
    tc_fence_before();
    __syncthreads();
    if (wid == 0) tc_dealloc(tmem, 512);
#else
    const int cc = (cnt + 255) & ~255;
    for (int o = tid; o < 256 * 128; o += 256) {
        int r = o >> 7, c = o & 127;
        int p = posBase + r;
        if (p >= cc) continue;
        const __half* xr = g_xg + ((size_t)e * TOK + p) * HID;
        const __half* w1r = g_w13h + ((size_t)e * FFN * 2 + (size_t)(fBaseF + c) * 2) * HID;
        const __half* w3r = w1r + HID;
        float a = 0.f, b = 0.f;
        for (int k = 0; k < HID; k++) {
            float xv = __half2float(xr[k]);
            a += xv * __half2float(w1r[k]);
            b += xv * __half2float(w3r[k]);
        }
        float s = a / (1.f + __expf(-a));
        g_h[((size_t)e * TOK + p) * FFN + fBaseF + c] = __float2half(s * b);
    }
#endif
}

__global__ __launch_bounds__(256, 1) void gemm2_kernel(
    const __grid_constant__ CUtensorMap tmA, const __grid_constant__ CUtensorMap tmB) {
    const int e = blockIdx.z;
    const int cnt = g_counts[e];
    const int posBase = blockIdx.x * 256;       // token tile (fast dim)
    if (posBase >= cnt) return;
    const int nBase = blockIdx.y * 256;         // HID col base
    const int tid = threadIdx.x, wid = tid >> 5, lid = tid & 31;

#if TC_OK
    extern __shared__ char smem_raw[];
    uint32_t sb = smem_u32(smem_raw);
    sb = (sb + 1023) & ~1023u;
    const uint32_t BAR = sb + NSTG * STAGE_BYTES;

    if (tid == 0) {
#pragma unroll
        for (int s = 0; s < NSTG; s++) {
            mbar_init(BAR + 16 + 8 * s, 1);
            mbar_init(BAR + 48 + 8 * s, 1);
        }
        mbar_init(BAR + 80, 1);
    }
    if (wid == 0) tc_alloc(BAR, 512);
    __syncthreads();
    uint32_t tmem;
    asm volatile("ld.shared.b32 %0, [%1];" : "=r"(tmem) : "r"(BAR));

    const int NT = FFN / 64;
    if (tid == 0) {
        int s = 0, ph = 1;
        for (int it = 0; it < NT; it++) {
            mbar_wait(BAR + 48 + 8 * s, ph);
            mbar_expect_tx(BAR + 16 + 8 * s, STAGE_BYTES);
            tma3(sb + s * STAGE_BYTES,         &tmA, it * 64, posBase, e, BAR + 16 + 8 * s);
            tma3(sb + s * STAGE_BYTES + 32768, &tmB, it * 64, nBase,   e, BAR + 16 + 8 * s);
            if (++s == NSTG) { s = 0; ph ^= 1; }
        }
    } else if (tid == 32) {
        tc_fence_after();
        int s = 0, ph = 0;
        for (int it = 0; it < NT; it++) {
            mbar_wait(BAR + 16 + 8 * s, ph);
            uint64_t ad = smem_desc(sb + s * STAGE_BYTES);
            uint64_t bd = smem_desc(sb + s * STAGE_BYTES + 32768);
#pragma unroll
            for (int k = 0; k < 4; k++) {
                uint32_t en = (it | k) != 0;
                mma_f16_ss(tmem,       ad + k * 2,        bd + k * 2, IDESC, en);
                mma_f16_ss(tmem + 256, ad + 1024 + k * 2, bd + k * 2, IDESC, en);
            }
            tc_commit(BAR + 48 + 8 * s);
            if (++s == NSTG) { s = 0; ph ^= 1; }
        }
        tc_commit(BAR + 80);
    }
    mbar_wait(BAR + 80, 0);
    tc_fence_after();

    const int half = wid >> 2;
    const int p = posBase + half * 128 + (wid & 3) * 32 + lid;
    float* dst = g_y + ((size_t)e * TOK + p) * HID + nBase;
    const uint32_t tmb = tmem + half * 256;
#pragma unroll
    for (int c = 0; c < 8; c++) {
        uint32_t r[32];
        LDTM32(r, tmb + c * 32);
        tc_wait_ld();
        if (p < cnt) {
#pragma unroll
            for (int j = 0; j < 8; j++) {
                float4 f = make_float4(__uint_as_float(r[4 * j]), __uint_as_float(r[4 * j + 1]),
                                       __uint_as_float(r[4 * j + 2]), __uint_as_float(r[4 * j + 3]));
                reinterpret_cast<float4*>(dst + c * 32)[j] = f;
            }
        }
    }
    tc_fence_before();
    __syncthreads();
    if (wid == 0) tc_dealloc(tmem, 512);
#else
    for (int o = tid; o < 256 * 256; o += 256) {
        int r = o >> 8, c = o & 255;
        int p = posBase + r;
        if (p >= cnt) continue;
        const __half* hr = g_h + ((size_t)e * TOK + p) * FFN;
        const __half* wr = g_w2h + ((size_t)e * HID + nBase + c) * FFN;
        float a = 0.f;
        for (int k = 0; k < FFN; k++) a += __half2float(hr[k]) * __half2float(wr[k]);
        g_y[((size_t)e * TOK + p) * HID + nBase + c] = a;
    }
#endif
}

// ---------------- combine ----------------
__global__ void combine_kernel(float* __restrict__ out) {
    int v = blockIdx.x * blockDim.x + threadIdx.x;
    int t  = v >> 9;
    int dv = v & 511;
    float w0 = g_wt[2 * t], w1 = g_wt[2 * t + 1];
    int s0 = g_slot[2 * t], s1 = g_slot[2 * t + 1];
    float4 a = reinterpret_cast<const float4*>(g_y + (size_t)s0 * HID)[dv];
    float4 b = reinterpret_cast<const float4*>(g_y + (size_t)s1 * HID)[dv];
    float4 r;
    r.x = w0 * a.x + w1 * b.x;
    r.y = w0 * a.y + w1 * b.y;
    r.z = w0 * a.z + w1 * b.z;
    r.w = w0 * a.w + w1 * b.w;
    reinterpret_cast<float4*>(out)[v] = r;
}

// ---------------- host ----------------
typedef CUresult (*PFN_encode)(CUtensorMap*, CUtensorMapDataType, cuuint32_t, void*,
                               const cuuint64_t*, const cuuint64_t*, const cuuint32_t*,
                               const cuuint32_t*, CUtensorMapInterleave, CUtensorMapSwizzle,
                               CUtensorMapL2promotion, CUtensorMapFloatOOBfill);

static CUtensorMap s_tmA13, s_tmB13, s_tmA2, s_tmB2;
static cudaStream_t s_conv;
static cudaEvent_t  s_evFork, s_evA, s_evB, s_evC2;
static bool s_init = false;

static void encode_map(PFN_encode enc, CUtensorMap* tm, void* ptr,
                       uint64_t d0, uint64_t d1, uint64_t d2, uint32_t boxRows) {
    cuuint64_t dims[3]    = { d0, d1, d2 };
    cuuint64_t strides[2] = { d0 * 2, d0 * d1 * 2 };
    cuuint32_t box[3]     = { 64, boxRows, 1 };
    cuuint32_t es[3]      = { 1, 1, 1 };
    enc(tm, CU_TENSOR_MAP_DATA_TYPE_FLOAT16, 3, ptr, dims, strides, box, es,
        CU_TENSOR_MAP_INTERLEAVE_NONE, CU_TENSOR_MAP_SWIZZLE_128B,
        CU_TENSOR_MAP_L2_PROMOTION_L2_128B, CU_TENSOR_MAP_FLOAT_OOB_FILL_NONE);
}

extern "C" void kernel_launch(void* const* d_in, const int* in_sizes, int n_in,
                              void* d_out, int out_size) {
    const float* x  = (const float*)d_in[0];
    const float* wg = (const float*)d_in[1];
    const float* w1 = (const float*)d_in[2];
    const float* w2 = (const float*)d_in[3];
    const float* w3 = (const float*)d_in[4];
    float* out = (float*)d_out;

    if (!s_init) {
        void* fn = nullptr;
        cudaDriverEntryPointQueryResult qr;
        cudaGetDriverEntryPoint("cuTensorMapEncodeTiled", &fn, cudaEnableDefault, &qr);
        PFN_encode enc = (PFN_encode)fn;
        void *pxg, *pw13, *pw2, *ph;
        cudaGetSymbolAddress(&pxg,  g_xg);
        cudaGetSymbolAddress(&pw13, g_w13h);
        cudaGetSymbolAddress(&pw2,  g_w2h);
        cudaGetSymbolAddress(&ph,   g_h);
        encode_map(enc, &s_tmA13, pxg,  HID, TOK,     NEXP, 256);
        encode_map(enc, &s_tmB13, pw13, HID, 2 * FFN, NEXP, 256);
        encode_map(enc, &s_tmA2,  ph,   FFN, TOK,     NEXP, 256);
        encode_map(enc, &s_tmB2,  pw2,  FFN, HID,     NEXP, 256);
        cudaFuncSetAttribute(gemm13_kernel, cudaFuncAttributeMaxDynamicSharedMemorySize, SMEM_REQ);
        cudaFuncSetAttribute(gemm2_kernel,  cudaFuncAttributeMaxDynamicSharedMemorySize, SMEM_REQ);
        cudaStreamCreateWithFlags(&s_conv, cudaStreamNonBlocking);
        cudaEventCreateWithFlags(&s_evFork, cudaEventDisableTiming);
        cudaEventCreateWithFlags(&s_evA,    cudaEventDisableTiming);
        cudaEventCreateWithFlags(&s_evB,    cudaEventDisableTiming);
        cudaEventCreateWithFlags(&s_evC2,   cudaEventDisableTiming);
        s_init = true;
    }

    // fork: conversions on side stream (two w13 halves, then w2)
    cudaEventRecord(s_evFork, 0);
    cudaStreamWaitEvent(s_conv, s_evFork, 0);
    conv_w13_kernel<<<dim3(FFN * 2 * (HID / 8) / 256, 1, 4), 256, 0, s_conv>>>(w1, w3, 0);
    cudaEventRecord(s_evA, s_conv);
    conv_w13_kernel<<<dim3(FFN * 2 * (HID / 8) / 256, 1, 4), 256, 0, s_conv>>>(w1, w3, 4);
    cudaEventRecord(s_evB, s_conv);
    conv_w2_kernel<<<dim3(HID * (FFN / 8) / 256, 1, NEXP), 256, 0, s_conv>>>(w2);
    cudaEventRecord(s_evC2, s_conv);

    // main: router (+fused scatter) then pad
    zero_counts_kernel<<<1, 32>>>();
    router_kernel<<<(TOK * 32) / 256, 256>>>(x, wg);
    pad_kernel<<<dim3(256, NEXP), 256>>>();

    // gemm13 in two 4-expert chunks; token tile = blockIdx.x (fast) for L2 reuse
    cudaStreamWaitEvent(0, s_evA, 0);
    gemm13_kernel<<<dim3(TOK / 256, 2 * FFN / 256, 4), 256, SMEM_REQ>>>(0, s_tmA13, s_tmB13);
    cudaStreamWaitEvent(0, s_evB, 0);
    gemm13_kernel<<<dim3(TOK / 256, 2 * FFN / 256, 4), 256, SMEM_REQ>>>(4, s_tmA13, s_tmB13);

    cudaStreamWaitEvent(0, s_evC2, 0);
    gemm2_kernel<<<dim3(TOK / 256, HID / 256, NEXP), 256, SMEM_REQ>>>(s_tmA2, s_tmB2);
    combine_kernel<<<(TOK * HID / 4) / 256, 256>>>(out);
}

// round 16
// speedup vs baseline: 1.0287x; 1.0287x over previous
#include <cuda_runtime.h>
#include <cuda.h>
#include <cuda_fp16.h>
#include <cstdint>

#define TOK  2048
#define HID  2048
#define FFN  5632
#define NEXP 8
#define NSTG 3
#define STAGE_BYTES 65536          // A fp16 32KB + B fp16 32KB
#define SMEM_REQ (1024 + NSTG * STAGE_BYTES + 256)

// ---- arch feature gate ----
#if !defined(__CUDA_ARCH__)
#  define TC_OK 1
#elif defined(__CUDA_ARCH_FEAT_SM103_ALL) || defined(__CUDA_ARCH_FEAT_SM100_ALL) || \
      defined(__CUDA_ARCH_FEAT_SM101_ALL) || \
      (defined(__CUDA_ARCH_SPECIFIC__) && (__CUDA_ARCH_SPECIFIC__ >= 1000)) || \
      (defined(__CUDA_ARCH_FAMILY_SPECIFIC__) && (__CUDA_ARCH_FAMILY_SPECIFIC__ >= 1000))
#  define TC_OK 1
#else
#  define TC_OK 0
#endif

// ---------------- static scratch ----------------
__device__ int   g_counts[NEXP];
__device__ int   g_slot[TOK * 2];
__device__ float g_wt[TOK * 2];
__device__ __align__(1024) __half g_xg[(size_t)NEXP * TOK * HID];
__device__ __align__(1024) __half g_w13h[(size_t)NEXP * FFN * 2 * HID];
__device__ __align__(1024) __half g_w2h[(size_t)NEXP * HID * FFN];
__device__ __align__(1024) __half g_h[(size_t)NEXP * TOK * FFN];
__device__ __align__(1024) float  g_y[(size_t)NEXP * TOK * HID];

// ---------------- PTX helpers ----------------
__device__ __forceinline__ uint32_t smem_u32(const void* p) {
    uint32_t a;
    asm("{ .reg .u64 t; cvta.to.shared.u64 t, %1; cvt.u32.u64 %0, t; }" : "=r"(a) : "l"(p));
    return a;
}
__device__ __forceinline__ uint32_t ctarank() {
    uint32_t r; asm("mov.u32 %0, %%cluster_ctarank;" : "=r"(r)); return r;
}
__device__ __forceinline__ void cluster_sync() {
    asm volatile("barrier.cluster.arrive.aligned;" ::: "memory");
    asm volatile("barrier.cluster.wait.aligned;" ::: "memory");
}
__device__ __forceinline__ void mbar_init(uint32_t a, uint32_t cnt) {
    asm volatile("mbarrier.init.shared.b64 [%0], %1;" :: "r"(a), "r"(cnt) : "memory");
}
__device__ __forceinline__ void mbar_expect_tx(uint32_t a, uint32_t bytes) {
    asm volatile("mbarrier.arrive.expect_tx.shared.b64 _, [%0], %1;" :: "r"(a), "r"(bytes) : "memory");
}
__device__ __forceinline__ void mbar_wait(uint32_t a, uint32_t phase) {
    uint32_t done;
    asm volatile(
        "{\n\t.reg .pred p;\n\t"
        "mbarrier.try_wait.parity.acquire.cta.shared::cta.b64 p, [%1], %2;\n\t"
        "selp.b32 %0, 1, 0, p;\n\t}"
        : "=r"(done) : "r"(a), "r"(phase) : "memory");
    if (!done) {
        asm volatile(
            "{\n\t.reg .pred P1;\n\t"
            "W_%=:\n\t"
            "mbarrier.try_wait.parity.acquire.cta.shared::cta.b64 P1, [%0], %1, 0x989680;\n\t"
            "@P1 bra.uni D_%=;\n\t"
            "bra.uni W_%=;\n\t"
            "D_%=:\n\t}"
            :: "r"(a), "r"(phase) : "memory");
    }
}
__device__ __forceinline__ void tma3(uint32_t smem_dst, const CUtensorMap* tm,
                                     int cx, int cy, int cz, uint32_t mbar) {
    asm volatile(
        "cp.async.bulk.tensor.3d.shared::cta.global.tile.mbarrier::complete_tx::bytes "
        "[%0], [%1, {%2, %3, %4}], [%5];"
        :: "r"(smem_dst), "l"(tm), "r"(cx), "r"(cy), "r"(cz), "r"(mbar) : "memory");
}
__device__ __forceinline__ void tma3_mc(uint32_t smem_dst, const CUtensorMap* tm,
                                        int cx, int cy, int cz, uint32_t mbar, uint16_t mask) {
    asm volatile(
        "cp.async.bulk.tensor.3d.shared::cluster.global.tile.mbarrier::complete_tx::bytes"
        ".multicast::cluster [%0], [%1, {%2, %3, %4}], [%5], %6;"
        :: "r"(smem_dst), "l"(tm), "r"(cx), "r"(cy), "r"(cz), "r"(mbar), "h"(mask) : "memory");
}
__device__ __forceinline__ void tc_alloc(uint32_t smem_result, uint32_t ncols) {
    asm volatile("tcgen05.alloc.cta_group::1.sync.aligned.shared::cta.b32 [%0], %1;"
                 :: "r"(smem_result), "r"(ncols) : "memory");
}
__device__ __forceinline__ void tc_dealloc(uint32_t tmem, uint32_t ncols) {
    asm volatile("tcgen05.dealloc.cta_group::1.sync.aligned.b32 %0, %1;" :: "r"(tmem), "r"(ncols));
}
__device__ __forceinline__ void tc_commit(uint32_t mbar) {
    asm volatile("tcgen05.commit.cta_group::1.mbarrier::arrive::one.shared::cluster.b64 [%0];"
                 :: "r"(mbar) : "memory");
}
__device__ __forceinline__ void tc_commit_mc(uint32_t mbar, uint16_t mask) {
    asm volatile("tcgen05.commit.cta_group::1.mbarrier::arrive::one.shared::cluster"
                 ".multicast::cluster.b64 [%0], %1;"
                 :: "r"(mbar), "h"(mask) : "memory");
}
__device__ __forceinline__ void tc_fence_after() {
    asm volatile("tcgen05.fence::after_thread_sync;" ::: "memory");
}
__device__ __forceinline__ void tc_fence_before() {
    asm volatile("tcgen05.fence::before_thread_sync;" ::: "memory");
}
__device__ __forceinline__ void tc_wait_ld() {
    asm volatile("tcgen05.wait::ld.sync.aligned;" ::: "memory");
}
__device__ __forceinline__ void mma_f16_ss(uint32_t d, uint64_t ad, uint64_t bd,
                                           uint32_t idesc, uint32_t en) {
    asm volatile(
        "{\n\t.reg .pred p;\n\t"
        "setp.ne.u32 p, %4, 0;\n\t"
        "tcgen05.mma.cta_group::1.kind::f16 [%0], %1, %2, %3, {%5, %5, %5, %5}, p;\n\t}"
        :: "r"(d), "l"(ad), "l"(bd), "r"(idesc), "r"(en), "r"(0u) : "memory");
}
#define LDTM32(r, addr) \
    asm volatile("tcgen05.ld.sync.aligned.32x32b.x32.b32 " \
        "{%0,%1,%2,%3,%4,%5,%6,%7,%8,%9,%10,%11,%12,%13,%14,%15," \
        "%16,%17,%18,%19,%20,%21,%22,%23,%24,%25,%26,%27,%28,%29,%30,%31}, [%32];" \
        : "=r"((r)[0]),"=r"((r)[1]),"=r"((r)[2]),"=r"((r)[3]),"=r"((r)[4]),"=r"((r)[5]), \
          "=r"((r)[6]),"=r"((r)[7]),"=r"((r)[8]),"=r"((r)[9]),"=r"((r)[10]),"=r"((r)[11]), \
          "=r"((r)[12]),"=r"((r)[13]),"=r"((r)[14]),"=r"((r)[15]),"=r"((r)[16]),"=r"((r)[17]), \
          "=r"((r)[18]),"=r"((r)[19]),"=r"((r)[20]),"=r"((r)[21]),"=r"((r)[22]),"=r"((r)[23]), \
          "=r"((r)[24]),"=r"((r)[25]),"=r"((r)[26]),"=r"((r)[27]),"=r"((r)[28]),"=r"((r)[29]), \
          "=r"((r)[30]),"=r"((r)[31]) : "r"(addr))

static constexpr uint64_t DESC_BASE_SW128 =
    (uint64_t(2) << 61) | (uint64_t(1) << 46) | (uint64_t(64) << 32) | (uint64_t(1) << 16);
__device__ __forceinline__ uint64_t smem_desc(uint32_t addr) {
    return DESC_BASE_SW128 | ((uint64_t)(addr >> 4) & 0x3FFF);
}
#define IDESC ((1u << 4) | (32u << 17) | (8u << 24))

// ---------------- small kernels ----------------
__global__ void zero_counts_kernel() { if (threadIdx.x < NEXP) g_counts[threadIdx.x] = 0; }

__global__ void conv_w13_kernel(const float* __restrict__ w1, const float* __restrict__ w3) {
    int e = blockIdx.z;
    int v = blockIdx.x * blockDim.x + threadIdx.x;
    int rr = v >> 8;
    int c8 = (v & 255) * 8;
    int f = rr >> 1;
    const float* src = ((rr & 1) ? w3 : w1) + ((size_t)e * FFN + f) * HID + c8;
    float4 f0 = reinterpret_cast<const float4*>(src)[0];
    float4 f1 = reinterpret_cast<const float4*>(src)[1];
    __half2 h0 = __floats2half2_rn(f0.x, f0.y), h1 = __floats2half2_rn(f0.z, f0.w);
    __half2 h2 = __floats2half2_rn(f1.x, f1.y), h3 = __floats2half2_rn(f1.z, f1.w);
    uint4 u = { *(unsigned*)&h0, *(unsigned*)&h1, *(unsigned*)&h2, *(unsigned*)&h3 };
    *reinterpret_cast<uint4*>(g_w13h + ((size_t)e * FFN * 2 + rr) * HID + c8) = u;
}

__global__ void conv_w2_kernel(const float* __restrict__ w2) {
    int e = blockIdx.z;
    int v = blockIdx.x * blockDim.x + threadIdx.x;
    int row = v / (FFN / 8);
    int c8 = (v % (FFN / 8)) * 8;
    const float* src = w2 + ((size_t)e * HID + row) * FFN + c8;
    float4 f0 = reinterpret_cast<const float4*>(src)[0];
    float4 f1 = reinterpret_cast<const float4*>(src)[1];
    __half2 h0 = __floats2half2_rn(f0.x, f0.y), h1 = __floats2half2_rn(f0.z, f0.w);
    __half2 h2 = __floats2half2_rn(f1.x, f1.y), h3 = __floats2half2_rn(f1.z, f1.w);
    uint4 u = { *(unsigned*)&h0, *(unsigned*)&h1, *(unsigned*)&h2, *(unsigned*)&h3 };
    *reinterpret_cast<uint4*>(g_w2h + ((size_t)e * HID + row) * FFN + c8) = u;
}

// router + fused fp16 scatter (pad rows left as-is: deterministic, M-rows independent)
__global__ void router_kernel(const float* __restrict__ x, const float* __restrict__ wg) {
    int gw   = (blockIdx.x * blockDim.x + threadIdx.x) >> 5;
    int lane = threadIdx.x & 31;
    if (gw >= TOK) return;
    const float4* xr = reinterpret_cast<const float4*>(x + (size_t)gw * HID);
    float acc[NEXP];
#pragma unroll
    for (int e = 0; e < NEXP; e++) acc[e] = 0.f;
#pragma unroll 4
    for (int it = 0; it < 16; it++) {
        float4 xv = xr[lane + 32 * it];
#pragma unroll
        for (int e = 0; e < NEXP; e++) {
            float4 w = reinterpret_cast<const float4*>(wg + e * HID)[lane + 32 * it];
            acc[e] += xv.x * w.x + xv.y * w.y + xv.z * w.z + xv.w * w.w;
        }
    }
#pragma unroll
    for (int e = 0; e < NEXP; e++) {
#pragma unroll
        for (int o = 16; o > 0; o >>= 1) acc[e] += __shfl_xor_sync(0xffffffffu, acc[e], o);
    }
    int e0 = 0, e1 = 0, q0 = 0, q1 = 0;
    if (lane == 0) {
        float m = acc[0];
#pragma unroll
        for (int e = 1; e < NEXP; e++) m = fmaxf(m, acc[e]);
        float p[NEXP];
#pragma unroll
        for (int e = 0; e < NEXP; e++) p[e] = __expf(acc[e] - m);
        e0 = 0;
#pragma unroll
        for (int e = 1; e < NEXP; e++) if (p[e] > p[e0]) e0 = e;
        e1 = (e0 == 0) ? 1 : 0;
#pragma unroll
        for (int e = 0; e < NEXP; e++) if (e != e0 && p[e] > p[e1]) e1 = e;
        float s  = p[e0] + p[e1];
        q0 = atomicAdd(&g_counts[e0], 1);
        q1 = atomicAdd(&g_counts[e1], 1);
        g_slot[2 * gw]     = e0 * TOK + q0;  g_wt[2 * gw]     = p[e0] / s;
        g_slot[2 * gw + 1] = e1 * TOK + q1;  g_wt[2 * gw + 1] = p[e1] / s;
    }
    e0 = __shfl_sync(0xffffffffu, e0, 0);
    e1 = __shfl_sync(0xffffffffu, e1, 0);
    q0 = __shfl_sync(0xffffffffu, q0, 0);
    q1 = __shfl_sync(0xffffffffu, q1, 0);
    uint2* d0 = reinterpret_cast<uint2*>(g_xg + ((size_t)e0 * TOK + q0) * HID);
    uint2* d1 = reinterpret_cast<uint2*>(g_xg + ((size_t)e1 * TOK + q1) * HID);
#pragma unroll 4
    for (int it = 0; it < 16; it++) {
        float4 xv = xr[lane + 32 * it];
        __half2 h0 = __floats2half2_rn(xv.x, xv.y);
        __half2 h1 = __floats2half2_rn(xv.z, xv.w);
        uint2 u = { *(unsigned*)&h0, *(unsigned*)&h1 };
        d0[lane + 32 * it] = u;
        d1[lane + 32 * it] = u;
    }
}

// ======= tcgen05 GEMMs: M=256, N=256, K-stage=64, TMA + A-multicast (cluster 2 over n) =======
// grid: x = n-tile (cluster dim), y = token-tile, z = expert. Both cluster members share
// (y,z) -> identical A tile: rank0 multicasts A to both; B loaded per-CTA.
// Barriers: full[s] (cnt 1, expect 64KB), mmadone[s] (cnt 2, both CTAs' commit-mcast), done (cnt 1).

__global__ __launch_bounds__(256, 1) __cluster_dims__(2, 1, 1) void gemm13_kernel(
    const __grid_constant__ CUtensorMap tmA, const __grid_constant__ CUtensorMap tmB) {
    const int e = blockIdx.z;
    const int cnt = g_counts[e];
    const int posBase = blockIdx.y * 256;
    if (posBase >= cnt) return;      // whole cluster exits together (same y,z)
    const int nBase = blockIdx.x * 256;
    const int fBaseF = blockIdx.x * 128;
    const int tid = threadIdx.x, wid = tid >> 5, lid = tid & 31;

#if TC_OK
    extern __shared__ char smem_raw[];
    uint32_t sb = smem_u32(smem_raw);
    sb = (sb + 1023) & ~1023u;
    const uint32_t BAR = sb + NSTG * STAGE_BYTES;
    const uint32_t rank = ctarank();

    if (tid == 0) {
#pragma unroll
        for (int s = 0; s < NSTG; s++) {
            mbar_init(BAR + 16 + 8 * s, 1);   // full
            mbar_init(BAR + 48 + 8 * s, 2);   // mmadone (both CTAs' commits)
        }
        mbar_init(BAR + 80, 1);               // done
    }
    if (wid == 0) tc_alloc(BAR, 512);
    __syncthreads();
    cluster_sync();                            // peer barriers initialized before multicast
    uint32_t tmem;
    asm volatile("ld.shared.b32 %0, [%1];" : "=r"(tmem) : "r"(BAR));

    const int NT = HID / 64;
    if (tid == 0) {             // TMA producer
        int s = 0, ph = 1;
        for (int it = 0; it < NT; it++) {
            mbar_wait(BAR + 48 + 8 * s, ph);
            mbar_expect_tx(BAR + 16 + 8 * s, STAGE_BYTES);
            if (rank == 0)
                tma3_mc(sb + s * STAGE_BYTES, &tmA, it * 64, posBase, e,
                        BAR + 16 + 8 * s, 0x3);
            tma3(sb + s * STAGE_BYTES + 32768, &tmB, it * 64, nBase, e, BAR + 16 + 8 * s);
            if (++s == NSTG) { s = 0; ph ^= 1; }
        }
    } else if (tid == 32) {     // MMA driver
        tc_fence_after();
        int s = 0, ph = 0;
        for (int it = 0; it < NT; it++) {
            mbar_wait(BAR + 16 + 8 * s, ph);
            uint64_t ad = smem_desc(sb + s * STAGE_BYTES);
            uint64_t bd = smem_desc(sb + s * STAGE_BYTES + 32768);
#pragma unroll
            for (int k = 0; k < 4; k++) {
                uint32_t en = (it | k) != 0;
                mma_f16_ss(tmem,       ad + k * 2,        bd + k * 2, IDESC, en);
                mma_f16_ss(tmem + 256, ad + 1024 + k * 2, bd + k * 2, IDESC, en);
            }
            tc_commit_mc(BAR + 48 + 8 * s, 0x3);   // arrive both CTAs' mmadone[s]
            if (++s == NSTG) { s = 0; ph ^= 1; }
        }
        tc_commit(BAR + 80);
    }
    mbar_wait(BAR + 80, 0);
    tc_fence_after();

    const int half = wid >> 2;
    const int p = posBase + half * 128 + (wid & 3) * 32 + lid;
    __half* dst = g_h + ((size_t)e * TOK + p) * FFN + fBaseF;
    const uint32_t tmb = tmem + half * 256;
#pragma unroll
    for (int c = 0; c < 8; c++) {
        uint32_t r[32];
        LDTM32(r, tmb + c * 32);
        tc_wait_ld();
        if (p < cnt) {
            unsigned o[8];
#pragma unroll
            for (int j = 0; j < 8; j++) {
                float a0 = __uint_as_float(r[4 * j + 0]);
                float b0 = __uint_as_float(r[4 * j + 1]);
                float a1 = __uint_as_float(r[4 * j + 2]);
                float b1 = __uint_as_float(r[4 * j + 3]);
                float v0 = (a0 / (1.f + __expf(-a0))) * b0;
                float v1 = (a1 / (1.f + __expf(-a1))) * b1;
                __half2 hh = __floats2half2_rn(v0, v1);
                o[j] = *(unsigned*)&hh;
            }
            *reinterpret_cast<uint4*>(dst + c * 16)     = make_uint4(o[0], o[1], o[2], o[3]);
            *reinterpret_cast<uint4*>(dst + c * 16 + 8) = make_uint4(o[4], o[5], o[6], o[7]);
        }
    }
    tc_fence_before();
    __syncthreads();
    if (wid == 0) tc_dealloc(tmem, 512);
    cluster_sync();                            // no exit while peer mcast may target us
#else
    const int cc = (cnt + 255) & ~255;
    for (int o = tid; o < 256 * 128; o += 256) {
        int r = o >> 7, c = o & 127;
        int p = posBase + r;
        if (p >= cc) continue;
        const __half* xr = g_xg + ((size_t)e * TOK + p) * HID;
        const __half* w1r = g_w13h + ((size_t)e * FFN * 2 + (size_t)(fBaseF + c) * 2) * HID;
        const __half* w3r = w1r + HID;
        float a = 0.f, b = 0.f;
        for (int k = 0; k < HID; k++) {
            float xv = __half2float(xr[k]);
            a += xv * __half2float(w1r[k]);
            b += xv * __half2float(w3r[k]);
        }
        float s = a / (1.f + __expf(-a));
        if (p < cnt)
            g_h[((size_t)e * TOK + p) * FFN + fBaseF + c] = __float2half(s * b);
    }
#endif
}

__global__ __launch_bounds__(256, 1) __cluster_dims__(2, 1, 1) void gemm2_kernel(
    const __grid_constant__ CUtensorMap tmA, const __grid_constant__ CUtensorMap tmB) {
    const int e = blockIdx.z;
    const int cnt = g_counts[e];
    const int posBase = blockIdx.y * 256;
    if (posBase >= cnt) return;
    const int nBase = blockIdx.x * 256;
    const int tid = threadIdx.x, wid = tid >> 5, lid = tid & 31;

#if TC_OK
    extern __shared__ char smem_raw[];
    uint32_t sb = smem_u32(smem_raw);
    sb = (sb + 1023) & ~1023u;
    const uint32_t BAR = sb + NSTG * STAGE_BYTES;
    const uint32_t rank = ctarank();

    if (tid == 0) {
#pragma unroll
        for (int s = 0; s < NSTG; s++) {
            mbar_init(BAR + 16 + 8 * s, 1);
            mbar_init(BAR + 48 + 8 * s, 2);
        }
        mbar_init(BAR + 80, 1);
    }
    if (wid == 0) tc_alloc(BAR, 512);
    __syncthreads();
    cluster_sync();
    uint32_t tmem;
    asm volatile("ld.shared.b32 %0, [%1];" : "=r"(tmem) : "r"(BAR));

    const int NT = FFN / 64;
    if (tid == 0) {
        int s = 0, ph = 1;
        for (int it = 0; it < NT; it++) {
            mbar_wait(BAR + 48 + 8 * s, ph);
            mbar_expect_tx(BAR + 16 + 8 * s, STAGE_BYTES);
            if (rank == 0)
                tma3_mc(sb + s * STAGE_BYTES, &tmA, it * 64, posBase, e,
                        BAR + 16 + 8 * s, 0x3);
            tma3(sb + s * STAGE_BYTES + 32768, &tmB, it * 64, nBase, e, BAR + 16 + 8 * s);
            if (++s == NSTG) { s = 0; ph ^= 1; }
        }
    } else if (tid == 32) {
        tc_fence_after();
        int s = 0, ph = 0;
        for (int it = 0; it < NT; it++) {
            mbar_wait(BAR + 16 + 8 * s, ph);
            uint64_t ad = smem_desc(sb + s * STAGE_BYTES);
            uint64_t bd = smem_desc(sb + s * STAGE_BYTES + 32768);
#pragma unroll
            for (int k = 0; k < 4; k++) {
                uint32_t en = (it | k) != 0;
                mma_f16_ss(tmem,       ad + k * 2,        bd + k * 2, IDESC, en);
                mma_f16_ss(tmem + 256, ad + 1024 + k * 2, bd + k * 2, IDESC, en);
            }
            tc_commit_mc(BAR + 48 + 8 * s, 0x3);
            if (++s == NSTG) { s = 0; ph ^= 1; }
        }
        tc_commit(BAR + 80);
    }
    mbar_wait(BAR + 80, 0);
    tc_fence_after();

    const int half = wid >> 2;
    const int p = posBase + half * 128 + (wid & 3) * 32 + lid;
    float* dst = g_y + ((size_t)e * TOK + p) * HID + nBase;
    const uint32_t tmb = tmem + half * 256;
#pragma unroll
    for (int c = 0; c < 8; c++) {
        uint32_t r[32];
        LDTM32(r, tmb + c * 32);
        tc_wait_ld();
        if (p < cnt) {
#pragma unroll
            for (int j = 0; j < 8; j++) {
                float4 f = make_float4(__uint_as_float(r[4 * j]), __uint_as_float(r[4 * j + 1]),
                                       __uint_as_float(r[4 * j + 2]), __uint_as_float(r[4 * j + 3]));
                reinterpret_cast<float4*>(dst + c * 32)[j] = f;
            }
        }
    }
    tc_fence_before();
    __syncthreads();
    if (wid == 0) tc_dealloc(tmem, 512);
    cluster_sync();
#else
    for (int o = tid; o < 256 * 256; o += 256) {
        int r = o >> 8, c = o & 255;
        int p = posBase + r;
        if (p >= cnt) continue;
        const __half* hr = g_h + ((size_t)e * TOK + p) * FFN;
        const __half* wr = g_w2h + ((size_t)e * HID + nBase + c) * FFN;
        float a = 0.f;
        for (int k = 0; k < FFN; k++) a += __half2float(hr[k]) * __half2float(wr[k]);
        g_y[((size_t)e * TOK + p) * HID + nBase + c] = a;
    }
#endif
}

// ---------------- combine ----------------
__global__ void combine_kernel(float* __restrict__ out) {
    int v = blockIdx.x * blockDim.x + threadIdx.x;
    int t  = v >> 9;
    int dv = v & 511;
    float w0 = g_wt[2 * t], w1 = g_wt[2 * t + 1];
    int s0 = g_slot[2 * t], s1 = g_slot[2 * t + 1];
    float4 a = reinterpret_cast<const float4*>(g_y + (size_t)s0 * HID)[dv];
    float4 b = reinterpret_cast<const float4*>(g_y + (size_t)s1 * HID)[dv];
    float4 r;
    r.x = w0 * a.x + w1 * b.x;
    r.y = w0 * a.y + w1 * b.y;
    r.z = w0 * a.z + w1 * b.z;
    r.w = w0 * a.w + w1 * b.w;
    reinterpret_cast<float4*>(out)[v] = r;
}

// ---------------- host ----------------
typedef CUresult (*PFN_encode)(CUtensorMap*, CUtensorMapDataType, cuuint32_t, void*,
                               const cuuint64_t*, const cuuint64_t*, const cuuint32_t*,
                               const cuuint32_t*, CUtensorMapInterleave, CUtensorMapSwizzle,
                               CUtensorMapL2promotion, CUtensorMapFloatOOBfill);

static CUtensorMap s_tmA13, s_tmB13, s_tmA2, s_tmB2;
static cudaStream_t s_conv;
static cudaEvent_t  s_evFork, s_evA, s_evC2;
static bool s_init = false;

static void encode_map(PFN_encode enc, CUtensorMap* tm, void* ptr,
                       uint64_t d0, uint64_t d1, uint64_t d2, uint32_t boxRows) {
    cuuint64_t dims[3]    = { d0, d1, d2 };
    cuuint64_t strides[2] = { d0 * 2, d0 * d1 * 2 };
    cuuint32_t box[3]     = { 64, boxRows, 1 };
    cuuint32_t es[3]      = { 1, 1, 1 };
    enc(tm, CU_TENSOR_MAP_DATA_TYPE_FLOAT16, 3, ptr, dims, strides, box, es,
        CU_TENSOR_MAP_INTERLEAVE_NONE, CU_TENSOR_MAP_SWIZZLE_128B,
        CU_TENSOR_MAP_L2_PROMOTION_L2_128B, CU_TENSOR_MAP_FLOAT_OOB_FILL_NONE);
}

extern "C" void kernel_launch(void* const* d_in, const int* in_sizes, int n_in,
                              void* d_out, int out_size) {
    const float* x  = (const float*)d_in[0];
    const float* wg = (const float*)d_in[1];
    const float* w1 = (const float*)d_in[2];
    const float* w2 = (const float*)d_in[3];
    const float* w3 = (const float*)d_in[4];
    float* out = (float*)d_out;

    if (!s_init) {
        void* fn = nullptr;
        cudaDriverEntryPointQueryResult qr;
        cudaGetDriverEntryPoint("cuTensorMapEncodeTiled", &fn, cudaEnableDefault, &qr);
        PFN_encode enc = (PFN_encode)fn;
        void *pxg, *pw13, *pw2, *ph;
        cudaGetSymbolAddress(&pxg,  g_xg);
        cudaGetSymbolAddress(&pw13, g_w13h);
        cudaGetSymbolAddress(&pw2,  g_w2h);
        cudaGetSymbolAddress(&ph,   g_h);
        encode_map(enc, &s_tmA13, pxg,  HID, TOK,     NEXP, 256);
        encode_map(enc, &s_tmB13, pw13, HID, 2 * FFN, NEXP, 256);
        encode_map(enc, &s_tmA2,  ph,   FFN, TOK,     NEXP, 256);
        encode_map(enc, &s_tmB2,  pw2,  FFN, HID,     NEXP, 256);
        cudaFuncSetAttribute(gemm13_kernel, cudaFuncAttributeMaxDynamicSharedMemorySize, SMEM_REQ);
        cudaFuncSetAttribute(gemm2_kernel,  cudaFuncAttributeMaxDynamicSharedMemorySize, SMEM_REQ);
        cudaStreamCreateWithFlags(&s_conv, cudaStreamNonBlocking);
        cudaEventCreateWithFlags(&s_evFork, cudaEventDisableTiming);
        cudaEventCreateWithFlags(&s_evA,    cudaEventDisableTiming);
        cudaEventCreateWithFlags(&s_evC2,   cudaEventDisableTiming);
        s_init = true;
    }

    // launch order puts gemm13 4th (ncu -s 5 -c 1 profiles the 4th kernel launch)
    cudaEventRecord(s_evFork, 0);
    cudaStreamWaitEvent(s_conv, s_evFork, 0);
    conv_w13_kernel<<<dim3(FFN * 2 * (HID / 8) / 256, 1, NEXP), 256, 0, s_conv>>>(w1, w3);  // #1
    cudaEventRecord(s_evA, s_conv);

    zero_counts_kernel<<<1, 32>>>();                                                        // #2
    router_kernel<<<(TOK * 32) / 256, 256>>>(x, wg);                                        // #3

    cudaStreamWaitEvent(0, s_evA, 0);
    gemm13_kernel<<<dim3(2 * FFN / 256, TOK / 256, NEXP), 256, SMEM_REQ>>>(s_tmA13, s_tmB13); // #4

    conv_w2_kernel<<<dim3(HID * (FFN / 8) / 256, 1, NEXP), 256, 0, s_conv>>>(w2);           // #5
    cudaEventRecord(s_evC2, s_conv);
    cudaStreamWaitEvent(0, s_evC2, 0);
    gemm2_kernel<<<dim3(HID / 256, TOK / 256, NEXP), 256, SMEM_REQ>>>(s_tmA2, s_tmB2);      // #6
    combine_kernel<<<(TOK * HID / 4) / 256, 256>>>(out);                                    // #7
}